// round 17
// baseline (speedup 1.0000x reference)
#include <cuda_runtime.h>
#include <cuda_fp16.h>
#include <stdint.h>
#include <math.h>

#define N_NODES 8192
#define F_IN    256
#define F_OUT   128
#define NWORDS  (N_NODES / 32)            // 256 bitmask words per row

// ---------------- scratch (__device__ globals: allocation-free rule) --------
__device__ float g_Wh[N_NODES * F_OUT];                  // 4 MB
__device__ float g_wh1[N_NODES];
__device__ float g_wh2[N_NODES];
__device__ float g_e2[N_NODES];                          // exp(wh2)
__device__ float g_f2[N_NODES];                          // exp(0.2*wh2)
__device__ __half g_WhT[F_OUT * N_NODES];                // 2 MB  [c][j]
__device__ uint32_t g_adjbits[N_NODES * NWORDS];         // 8 MB packed adj
__device__ float g_part[2][N_NODES * F_OUT];             // 8 MB partial numerators
__device__ float g_denp[2][N_NODES];                     // partial denominators

// ---------------- helpers ---------------------------------------------------
__device__ __forceinline__ uint32_t smem_u32(const void* p) {
    uint32_t a;
    asm("{ .reg .u64 t; cvta.to.shared.u64 t, %1; cvt.u32.u64 %0, t; }"
        : "=r"(a) : "l"(p));
    return a;
}
__device__ __forceinline__ void ldsm4(uint32_t* r, uint32_t addr) {
    asm volatile("ldmatrix.sync.aligned.m8n8.x4.shared.b16 {%0,%1,%2,%3}, [%4];"
                 : "=r"(r[0]), "=r"(r[1]), "=r"(r[2]), "=r"(r[3]) : "r"(addr));
}
__device__ __forceinline__ void mma16816(float* d, const uint32_t* a,
                                         const uint32_t* b) {
    asm volatile(
        "mma.sync.aligned.m16n8k16.row.col.f32.f16.f16.f32 "
        "{%0,%1,%2,%3}, {%4,%5,%6,%7}, {%8,%9}, {%0,%1,%2,%3};"
        : "+f"(d[0]), "+f"(d[1]), "+f"(d[2]), "+f"(d[3])
        : "r"(a[0]), "r"(a[1]), "r"(a[2]), "r"(a[3]), "r"(b[0]), "r"(b[1]));
}
// pack two floats -> f16x2 (first arg = low half)
__device__ __forceinline__ uint32_t pack2h(float lo, float hi) {
    uint32_t r;
    asm("cvt.rn.f16x2.f32 %0, %1, %2;" : "=r"(r) : "f"(hi), "f"(lo));
    return r;
}

// ---------------------------------------------------------------------------
// k0: bit-pack adjacency (warp ballot, fully coalesced, DRAM-streaming)
// ---------------------------------------------------------------------------
#define K0_BLOCKS 8192
__global__ void __launch_bounds__(256) k0_pack(const int* __restrict__ adj) {
    const size_t GT = (size_t)K0_BLOCKS * 256;
    const size_t gt = (size_t)blockIdx.x * 256 + threadIdx.x;
    const int lane = threadIdx.x & 31;
#pragma unroll 4
    for (int k = 0; k < 32; k++) {
        size_t idx = (size_t)k * GT + gt;
        int v = adj[idx];
        uint32_t w = __ballot_sync(0xffffffffu, v > 0);
        if (lane == 0) g_adjbits[idx >> 5] = w;
    }
}

// ---------------------------------------------------------------------------
// k1: Wh = h @ W ; fused epilogue computes wh1 = Wh.a1, wh2 = Wh.a2
// ---------------------------------------------------------------------------
__global__ void __launch_bounds__(256) k1_gemm(const float* __restrict__ h,
                                               const float* __restrict__ W,
                                               const float* __restrict__ a) {
    __shared__ float sA[16][64];
    __shared__ float sB[16][128];
    const int t  = threadIdx.x;
    const int ty = t >> 4;
    const int tx = t & 15;
    const int row0 = blockIdx.x * 64;

    float acc[4][8];
#pragma unroll
    for (int m = 0; m < 4; m++)
#pragma unroll
        for (int n = 0; n < 8; n++) acc[m][n] = 0.f;

    for (int k0 = 0; k0 < F_IN; k0 += 16) {
#pragma unroll
        for (int it = 0; it < 4; it++) {
            int idx = t + it * 256;
            int r = idx >> 4, kk = idx & 15;
            sA[kk][r] = h[(row0 + r) * F_IN + k0 + kk];
        }
#pragma unroll
        for (int it = 0; it < 8; it++) {
            int idx = t + it * 256;
            int kk = idx >> 7, c = idx & 127;
            sB[kk][c] = W[(k0 + kk) * F_OUT + c];
        }
        __syncthreads();
#pragma unroll
        for (int kk = 0; kk < 16; kk++) {
            float av[4], bv[8];
#pragma unroll
            for (int m = 0; m < 4; m++) av[m] = sA[kk][ty * 4 + m];
#pragma unroll
            for (int n = 0; n < 8; n++) bv[n] = sB[kk][tx * 8 + n];
#pragma unroll
            for (int m = 0; m < 4; m++)
#pragma unroll
                for (int n = 0; n < 8; n++) acc[m][n] += av[m] * bv[n];
        }
        __syncthreads();
    }
    float a1v[8], a2v[8];
#pragma unroll
    for (int n = 0; n < 8; n++) {
        a1v[n] = a[tx * 8 + n];
        a2v[n] = a[F_OUT + tx * 8 + n];
    }
#pragma unroll
    for (int m = 0; m < 4; m++) {
        int r = row0 + ty * 4 + m;
#pragma unroll
        for (int n = 0; n < 8; n++)
            g_Wh[r * F_OUT + tx * 8 + n] = acc[m][n];
        float p1 = 0.f, p2 = 0.f;
#pragma unroll
        for (int n = 0; n < 8; n++) {
            p1 += acc[m][n] * a1v[n];
            p2 += acc[m][n] * a2v[n];
        }
#pragma unroll
        for (int off = 8; off > 0; off >>= 1) {
            p1 += __shfl_down_sync(0xffffffffu, p1, off);
            p2 += __shfl_down_sync(0xffffffffu, p2, off);
        }
        if (tx == 0) { g_wh1[r] = p1; g_wh2[r] = p2; }
    }
}

// ---------------------------------------------------------------------------
// k2: transpose Wh -> WhT (fp16)
// ---------------------------------------------------------------------------
__global__ void __launch_bounds__(256) k2_transpose() {
    __shared__ float tile[32][33];
    const int tx = threadIdx.x & 31;
    const int ty = threadIdx.x >> 5;
    const int nb = blockIdx.x * 32;
    const int fb = blockIdx.y * 32;
#pragma unroll
    for (int rr = ty; rr < 32; rr += 8)
        tile[rr][tx] = g_Wh[(nb + rr) * F_OUT + fb + tx];
    __syncthreads();
#pragma unroll
    for (int rr = ty; rr < 32; rr += 8) {
        float v = tile[tx][rr];
        g_WhT[(size_t)(fb + rr) * N_NODES + nb + tx] = __float2half_rn(v);
    }
}

// ---------------------------------------------------------------------------
// k2b: per-node exp tables (separable leaky-exp)
// ---------------------------------------------------------------------------
__global__ void __launch_bounds__(256) k2b_exp() {
    int i = blockIdx.x * 256 + threadIdx.x;
    float w2 = g_wh2[i];
    g_e2[i] = __expf(w2);
    g_f2[i] = __expf(0.2f * w2);
}

// ---------------------------------------------------------------------------
// k3: fused attention, fp16 1-pass, bitmask adj, separable exp, dbuf overlap
// grid = 128 = 64 row-blocks x 2 j-splits; BM=128, BK=128 per chunk
// ---------------------------------------------------------------------------
#define BK 128
#define NCHUNK 32
#define TSTRIDE 272                       // bytes per tile row (128*2 + 16)
#define TILE_BYTES (128 * TSTRIDE)        // 34816
#define STAGE_BYTES (2 * TILE_BYTES)      // 69632
#define OFF_S(s)  ((s) * STAGE_BYTES)
#define OFF_B(s)  ((s) * STAGE_BYTES + TILE_BYTES)
#define OFF_E2    (2 * STAGE_BYTES)
#define OFF_F2    (OFF_E2 + 4096 * 4)
#define SMEM3     (OFF_F2 + 4096 * 4)     // 172,032 B

struct GenCtx {
    const __half*   srcB;     // WhT row pointer (thread's row, j-base)
    const uint32_t* bitp;     // packed adj row pointer (thread's j-base)
    const float*    sE2;
    const float*    sF2;
    uint32_t sbase, genRow;
    float E1, F1, TH;         // exp(wh1), exp(0.2 wh1), exp(-wh1)
};

__device__ __forceinline__ void gen_chunk(const GenCtx& g, int c, int jb,
                                          char* sm, float& den) {
    const int s = c & 1;
#pragma unroll
    for (int kk = 0; kk < 8; kk++) {
        uint4 vh = *(const uint4*)(g.srcB + (size_t)c * BK + kk * 8);
        uint32_t o = g.genRow + (uint32_t)(jb + kk * 8) * 2;
        *(uint4*)(sm + OFF_B(s) + o) = vh;
    }
    const uint2 mw = *(const uint2*)(g.bitp + c * (BK / 32));
#pragma unroll
    for (int kk = 0; kk < 16; kk++) {
        const int jl = jb + kk * 4;
        const uint32_t w = (kk < 8 ? mw.x : mw.y) >> ((kk * 4) & 31);
        const float4 e2 = *(const float4*)&g.sE2[c * BK + jl];
        const float4 f2 = *(const float4*)&g.sF2[c * BK + jl];
        float s0 = (w & 1u) ? (e2.x > g.TH ? g.E1 * e2.x : g.F1 * f2.x) : 0.f;
        float s1 = (w & 2u) ? (e2.y > g.TH ? g.E1 * e2.y : g.F1 * f2.y) : 0.f;
        float s2 = (w & 4u) ? (e2.z > g.TH ? g.E1 * e2.z : g.F1 * f2.z) : 0.f;
        float s3 = (w & 8u) ? (e2.w > g.TH ? g.E1 * e2.w : g.F1 * f2.w) : 0.f;
        den += (s0 + s1) + (s2 + s3);
        uint32_t h01 = pack2h(s0, s1), h23 = pack2h(s2, s3);
        uint32_t o = g.genRow + (uint32_t)jl * 2;
        asm volatile("st.shared.v2.b32 [%0], {%1,%2};"
                     :: "r"(g.sbase + OFF_S(s) + o), "r"(h01), "r"(h23));
    }
}

__global__ void __launch_bounds__(256, 1)
k3_attn() {
    extern __shared__ __align__(128) char sm[];
    const uint32_t sbase = smem_u32(sm);
    const int t   = threadIdx.x;
    const int wid = t >> 5;
    const int lid = t & 31;
    const int rb    = blockIdx.x >> 1;
    const int split = blockIdx.x & 1;
    const int row0  = rb * 128;
    const int jg0   = split * 4096;

    float* sE2 = (float*)(sm + OFF_E2);
    float* sF2 = (float*)(sm + OFF_F2);
#pragma unroll
    for (int i = 0; i < 16; i++) {
        sE2[t + i * 256] = g_e2[jg0 + t + i * 256];
        sF2[t + i * 256] = g_f2[jg0 + t + i * 256];
    }

    // ---- generation-stage mapping: thread -> (row r, j-half) ----
    const int r    = t >> 1;
    const int half = t & 1;
    const int jb   = half * 64;
    float den = 0.f;

    const float wh1r = g_wh1[row0 + r];
    GenCtx g;
    g.srcB   = g_WhT + (size_t)r * N_NODES + jg0 + jb;
    g.bitp   = g_adjbits + (size_t)(row0 + r) * NWORDS + ((jg0 + jb) >> 5);
    g.sE2    = sE2;
    g.sF2    = sF2;
    g.sbase  = sbase;
    g.genRow = (uint32_t)r * TSTRIDE;
    g.E1 = __expf(wh1r);
    g.F1 = __expf(0.2f * wh1r);
    g.TH = __expf(-wh1r);

    // ---- mma-stage mapping: 8 warps = 2(m) x 4(n); warp tile 64x32 ----
    const int warp_m = wid >> 2;
    const int warp_n = wid & 3;
    float d[4][4][4];
#pragma unroll
    for (int mf = 0; mf < 4; mf++)
#pragma unroll
        for (int nf = 0; nf < 4; nf++)
#pragma unroll
            for (int q = 0; q < 4; q++) d[mf][nf][q] = 0.f;

    const int gq = lid >> 3;
    const uint32_t aLane = (uint32_t)((gq & 1) * 8 + (lid & 7)) * TSTRIDE
                         + (uint32_t)((gq >> 1) * 8) * 2;
    const uint32_t bLane = (uint32_t)((gq >> 1) * 8 + (lid & 7)) * TSTRIDE
                         + (uint32_t)((gq & 1) * 8) * 2;
    const uint32_t aBase = sbase + (uint32_t)(warp_m * 64) * TSTRIDE + aLane;
    const uint32_t bBase = sbase + (uint32_t)(warp_n * 32) * TSTRIDE + bLane;

    __syncthreads();           // sE2/sF2 ready
    gen_chunk(g, 0, jb, sm, den);
    __syncthreads();           // buf0 ready

    for (int c = 0; c < NCHUNK; c++) {
        const int s = c & 1;

        if (c + 1 < NCHUNK)
            gen_chunk(g, c + 1, jb, sm, den);

        // ---- MMA: D += S * B ----
#pragma unroll
        for (int ks = 0; ks < 8; ks++) {
            uint32_t as[4][4], bh[2][4];
#pragma unroll
            for (int mf = 0; mf < 4; mf++) {
                uint32_t ad = aBase + (uint32_t)(mf * 16) * TSTRIDE + ks * 32;
                ldsm4(as[mf], ad + OFF_S(s));
            }
#pragma unroll
            for (int nf2 = 0; nf2 < 2; nf2++) {
                uint32_t bd = bBase + (uint32_t)(nf2 * 16) * TSTRIDE + ks * 32;
                ldsm4(bh[nf2], bd + OFF_B(s));
            }
#pragma unroll
            for (int mf = 0; mf < 4; mf++)
#pragma unroll
                for (int nf = 0; nf < 4; nf++)
                    mma16816(d[mf][nf], as[mf], &bh[nf >> 1][(nf & 1) * 2]);
        }
        __syncthreads();
    }

    // ---- partial denominator (combine j-halves within lane pair) ----
    float dsum = den + __shfl_xor_sync(0xffffffffu, den, 1);
    if (half == 0) g_denp[split][row0 + r] = dsum;

    // ---- partial numerator: register tiles -> g_part ----
    const int qr = lid >> 2;
    const int qc = (lid & 3) * 2;
    float* base = g_part[split] + (size_t)(row0 + warp_m * 64 + qr) * F_OUT
                + warp_n * 32 + qc;
#pragma unroll
    for (int mf = 0; mf < 4; mf++) {
#pragma unroll
        for (int nf = 0; nf < 4; nf++) {
            float* p = base + (size_t)(mf * 16) * F_OUT + nf * 8;
            *(float2*)p = make_float2(d[mf][nf][0], d[mf][nf][1]);
            *(float2*)(p + 8 * F_OUT) = make_float2(d[mf][nf][2], d[mf][nf][3]);
        }
    }
}

// ---------------------------------------------------------------------------
// k4: combine splits, divide, ELU
// ---------------------------------------------------------------------------
__global__ void __launch_bounds__(256) k4_combine(float* __restrict__ out) {
    int tid = blockIdx.x * 256 + threadIdx.x;
    int e = tid * 8;
    int row = e >> 7;
    float dinv = 1.0f / (g_denp[0][row] + g_denp[1][row]);
    const float4* p0 = (const float4*)(g_part[0] + e);
    const float4* p1 = (const float4*)(g_part[1] + e);
    float4* o = (float4*)(out + e);
#pragma unroll
    for (int q = 0; q < 2; q++) {
        float4 x = p0[q], y = p1[q];
        float v0 = (x.x + y.x) * dinv;
        float v1 = (x.y + y.y) * dinv;
        float v2 = (x.z + y.z) * dinv;
        float v3 = (x.w + y.w) * dinv;
        float4 r;
        r.x = (v0 > 0.f) ? v0 : expm1f(v0);
        r.y = (v1 > 0.f) ? v1 : expm1f(v1);
        r.z = (v2 > 0.f) ? v2 : expm1f(v2);
        r.w = (v3 > 0.f) ? v3 : expm1f(v3);
        o[q] = r;
    }
}

// ---------------------------------------------------------------------------
extern "C" void kernel_launch(void* const* d_in, const int* in_sizes, int n_in,
                              void* d_out, int out_size) {
    const float* h   = (const float*)d_in[0];
    const int*   adj = (const int*)  d_in[1];
    const float* W   = (const float*)d_in[2];
    const float* a   = (const float*)d_in[3];
    float* out = (float*)d_out;

    cudaFuncSetAttribute(k3_attn, cudaFuncAttributeMaxDynamicSharedMemorySize, SMEM3);

    k0_pack<<<K0_BLOCKS, 256>>>(adj);
    k1_gemm<<<N_NODES / 64, 256>>>(h, W, a);
    k2_transpose<<<dim3(N_NODES / 32, F_OUT / 32), 256>>>();
    k2b_exp<<<N_NODES / 256, 256>>>();
    k3_attn<<<128, 256, SMEM3>>>();
    k4_combine<<<512, 256>>>(out);
}